// round 3
// baseline (speedup 1.0000x reference)
#include <cuda_runtime.h>
#include <cstdint>

// PCEN, persistent 1-CTA/SM, 6-buffer deep-prefetch pipeline (depth 4):
//   ema_t = w*x_t + (1-w)*ema_{t-1}, ema_0 = x_0   (affine block scan, exact)
//   out   = (x/(FLOOR+ema)^a + d)^(1/root) - d^(1/root)
// B=128, C=64, T=8000. One row (8000 f32 = 32 KB) per buffer slot.

constexpr int      kT        = 8000;
constexpr int      kChunk    = 25;            // 320*25 = 8000; 25 coprime 32 -> no bank conflicts
constexpr int      kThreads  = 320;
constexpr int      kWarps    = kThreads / 32; // 10
constexpr int      kNBuf     = 6;
constexpr int      kPrefetch = 4;             // rows in flight ahead of compute
constexpr float    kFloor    = 1e-6f;
constexpr unsigned kRowBytes = kT * 4;        // 32000

__device__ __forceinline__ uint32_t s2u(const void* p) {
    return (uint32_t)__cvta_generic_to_shared(p);
}

__device__ __forceinline__ float sqrt_apx(float v) {
    float r;
    asm("sqrt.approx.f32 %0, %1;" : "=f"(r) : "f"(v));
    return r;
}

__device__ __forceinline__ void bulk_load(uint32_t dst_smem, const void* src_gmem,
                                          uint32_t bytes, uint32_t mbar) {
    asm volatile(
        "cp.async.bulk.shared::cta.global.mbarrier::complete_tx::bytes [%0], [%1], %2, [%3];"
        :: "r"(dst_smem), "l"(src_gmem), "r"(bytes), "r"(mbar) : "memory");
}

__device__ __forceinline__ void mbar_expect_tx(uint32_t mbar, uint32_t bytes) {
    asm volatile("mbarrier.arrive.expect_tx.shared::cta.b64 _, [%0], %1;"
                 :: "r"(mbar), "r"(bytes) : "memory");
}

__device__ __forceinline__ void mbar_wait(uint32_t mbar, uint32_t phase) {
    asm volatile(
        "{\n\t.reg .pred P;\n"
        "W_%=:\n\t"
        "mbarrier.try_wait.parity.acquire.cta.shared::cta.b64 P, [%0], %1, 0x989680;\n\t"
        "@!P bra W_%=;\n\t}"
        :: "r"(mbar), "r"(phase) : "memory");
}

__global__ void __launch_bounds__(kThreads, 1)
pcen_kernel(const float* __restrict__ x,
            const float* __restrict__ alpha,
            const float* __restrict__ delta,
            const float* __restrict__ root,
            const float* __restrict__ ew,
            float* __restrict__ out,
            int C, int rows)
{
    extern __shared__ float smem[];                      // kNBuf * kT floats
    __shared__ __align__(8) unsigned long long mbar[kNBuf];
    __shared__ float sA[kWarps], sB[kWarps];

    const int tid    = threadIdx.x;
    const int lane   = tid & 31;
    const int wid    = tid >> 5;
    const int stride = gridDim.x;

    if (tid == 0) {
        #pragma unroll
        for (int b = 0; b < kNBuf; ++b)
            asm volatile("mbarrier.init.shared::cta.b64 [%0], 1;"
                         :: "r"(s2u(&mbar[b])) : "memory");
    }
    __syncthreads();

    const int nIter = (rows - (int)blockIdx.x + stride - 1) / stride;

    // prologue: fill the prefetch ring
    if (tid == 0) {
        const int np = (kPrefetch < nIter) ? kPrefetch : nIter;
        for (int p = 0; p < np; ++p) {
            const uint32_t mb = s2u(&mbar[p]);
            mbar_expect_tx(mb, kRowBytes);
            bulk_load(s2u(smem + p * kT),
                      x + (size_t)(blockIdx.x + p * stride) * kT, kRowBytes, mb);
        }
    }

    for (int it = 0; it < nIter; ++it) {
        const int row  = blockIdx.x + it * stride;
        const int bsel = it % kNBuf;
        float* sx = smem + bsel * kT;

        // keep the ring full: load row it+kPrefetch into its buffer.
        // Buffer (it+4)%6 was last used by row it-2; its store must have
        // finished READING smem. Stores committed so far: rows <= it-1, so
        // allow 1 pending group (row it-1).
        if (tid == 0 && it + kPrefetch < nIter) {
            asm volatile("cp.async.bulk.wait_group.read 1;" ::: "memory");
            const int nb = (it + kPrefetch) % kNBuf;
            const uint32_t mb = s2u(&mbar[nb]);
            mbar_expect_tx(mb, kRowBytes);
            bulk_load(s2u(smem + nb * kT),
                      x + (size_t)(row + kPrefetch * stride) * kT, kRowBytes, mb);
        }

        // per-row params (uniform)
        const int   c  = row % C;
        const float w  = fminf(fmaxf(ew[c], 0.0f), 1.0f);
        const float q  = 1.0f - w;
        const float a  = fminf(alpha[c], 1.0f);
        const float d  = delta[c];
        const float r  = 1.0f / fmaxf(root[c], 1.0f);
        const bool  rhalf = (r == 0.5f);
        const float dr = rhalf ? sqrt_apx(d) : __powf(d, r);
        const float na = -a;

        // wait for this row's data (phase: buffer reused every kNBuf iters)
        mbar_wait(s2u(&mbar[bsel]), (it / kNBuf) & 1);

        const float x0  = sx[0];
        const int   off = tid * kChunk;

        // pass 1: stage chunk into registers + affine reduce (1 FMA/elem)
        float xv[kChunk];
        #pragma unroll
        for (int k = 0; k < kChunk; ++k) xv[k] = sx[off + k];

        float b = 0.0f;
        #pragma unroll
        for (int k = 0; k < kChunk; ++k) b = fmaf(q, b, xv[k]);
        b *= w;
        const float q2 = q*q, q4 = q2*q2, q8 = q4*q4, q16 = q8*q8;
        float A = q16 * q8 * q;   // q^25

        // warp inclusive scan of (A,b)
        #pragma unroll
        for (int s = 1; s < 32; s <<= 1) {
            float Ap = __shfl_up_sync(0xffffffffu, A, s);
            float bp = __shfl_up_sync(0xffffffffu, b, s);
            if (lane >= s) { b = fmaf(A, bp, b); A *= Ap; }
        }
        if (lane == 31) { sA[wid] = A; sB[wid] = b; }
        __syncthreads();

        if (wid == 0) {
            float Aw = (lane < kWarps) ? sA[lane] : 1.0f;
            float bw = (lane < kWarps) ? sB[lane] : 0.0f;
            #pragma unroll
            for (int s = 1; s < 16; s <<= 1) {
                float Ap = __shfl_up_sync(0xffffffffu, Aw, s);
                float bp = __shfl_up_sync(0xffffffffu, bw, s);
                if (lane >= s) { bw = fmaf(Aw, bp, bw); Aw *= Ap; }
            }
            if (lane < kWarps) { sA[lane] = Aw; sB[lane] = bw; }
        }
        __syncthreads();

        // exclusive prefix -> exact carry into this thread's chunk
        float Ai = __shfl_up_sync(0xffffffffu, A, 1);
        float bi = __shfl_up_sync(0xffffffffu, b, 1);
        if (lane == 0) { Ai = 1.0f; bi = 0.0f; }
        float Aex = Ai, bex = bi;
        if (wid > 0) {
            bex = fmaf(Ai, sB[wid - 1], bi);
            Aex = Ai * sA[wid - 1];
        }
        float acc = fmaf(Aex, x0, bex);

        // pass 2: EMA recompute + pointwise PCEN (x from registers)
        #pragma unroll
        for (int k = 0; k < kChunk; ++k) {
            const float xu = xv[k];
            acc = fmaf(q, acc, w * xu);
            const float p = __powf(kFloor + acc, na);      // LG2+FMUL+EX2
            const float u = fmaf(xu, p, d);
            const float y = rhalf ? sqrt_apx(u) : __powf(u, r);
            sx[off + k] = y - dr;
        }
        __syncthreads();

        // async bulk store smem -> gmem (overlaps subsequent compute)
        if (tid == 0) {
            asm volatile("fence.proxy.async.shared::cta;" ::: "memory");
            asm volatile("cp.async.bulk.global.shared::cta.bulk_group [%0], [%1], %2;"
                         :: "l"(out + (size_t)row * kT), "r"(s2u(sx)), "r"(kRowBytes)
                         : "memory");
            asm volatile("cp.async.bulk.commit_group;" ::: "memory");
        }
    }

    // smem is deallocated at CTA exit; stores must finish reading it first
    if (tid == 0)
        asm volatile("cp.async.bulk.wait_group 0;" ::: "memory");
}

extern "C" void kernel_launch(void* const* d_in, const int* in_sizes, int n_in,
                              void* d_out, int out_size)
{
    const float* x     = (const float*)d_in[0];
    const float* alpha = (const float*)d_in[1];
    const float* delta = (const float*)d_in[2];
    const float* root  = (const float*)d_in[3];
    const float* ew    = (const float*)d_in[4];
    float* out = (float*)d_out;

    const int C    = in_sizes[1];            // 64
    const int rows = in_sizes[0] / kT;       // 8192

    const unsigned smemBytes = kNBuf * kRowBytes;   // 192000
    cudaFuncSetAttribute(pcen_kernel, cudaFuncAttributeMaxDynamicSharedMemorySize, smemBytes);

    int grid = 148;                          // 1 persistent CTA per SM
    if (grid > rows) grid = rows;

    pcen_kernel<<<grid, kThreads, smemBytes>>>(x, alpha, delta, root, ew, out, C, rows);
}

// round 4
// speedup vs baseline: 1.7410x; 1.7410x over previous
#include <cuda_runtime.h>
#include <cstdint>

// PCEN, persistent 3-CTA/SM, double-buffered bulk-async pipeline:
//   ema_t = w*x_t + (1-w)*ema_{t-1}, ema_0 = x_0   (affine block scan, exact)
//   out   = (x/(FLOOR+ema)^a + d)^(1/root) - d^(1/root)
// B=128, C=64, T=8000. One row (8000 f32 = 32 KB) per buffer.

constexpr int      kT        = 8000;
constexpr int      kChunk    = 25;            // 320*25 = 8000; 25 coprime 32 -> no bank conflicts
constexpr int      kThreads  = 320;
constexpr int      kWarps    = kThreads / 32; // 10
constexpr int      kNBuf     = 2;
constexpr float    kFloor    = 1e-6f;
constexpr unsigned kRowBytes = kT * 4;        // 32000

__device__ __forceinline__ uint32_t s2u(const void* p) {
    return (uint32_t)__cvta_generic_to_shared(p);
}

__device__ __forceinline__ float sqrt_apx(float v) {
    float r;
    asm("sqrt.approx.f32 %0, %1;" : "=f"(r) : "f"(v));
    return r;
}

__device__ __forceinline__ void bulk_load(uint32_t dst_smem, const void* src_gmem,
                                          uint32_t bytes, uint32_t mbar) {
    asm volatile(
        "cp.async.bulk.shared::cta.global.mbarrier::complete_tx::bytes [%0], [%1], %2, [%3];"
        :: "r"(dst_smem), "l"(src_gmem), "r"(bytes), "r"(mbar) : "memory");
}

__device__ __forceinline__ void mbar_expect_tx(uint32_t mbar, uint32_t bytes) {
    asm volatile("mbarrier.arrive.expect_tx.shared::cta.b64 _, [%0], %1;"
                 :: "r"(mbar), "r"(bytes) : "memory");
}

__device__ __forceinline__ void mbar_wait(uint32_t mbar, uint32_t phase) {
    asm volatile(
        "{\n\t.reg .pred P;\n"
        "W_%=:\n\t"
        "mbarrier.try_wait.parity.acquire.cta.shared::cta.b64 P, [%0], %1, 0x989680;\n\t"
        "@!P bra W_%=;\n\t}"
        :: "r"(mbar), "r"(phase) : "memory");
}

__global__ void __launch_bounds__(kThreads, 3)
pcen_kernel(const float* __restrict__ x,
            const float* __restrict__ alpha,
            const float* __restrict__ delta,
            const float* __restrict__ root,
            const float* __restrict__ ew,
            float* __restrict__ out,
            int C, int rows)
{
    extern __shared__ float smem[];                      // kNBuf * kT floats
    __shared__ __align__(8) unsigned long long mbar[kNBuf];
    __shared__ float sA[kWarps], sB[kWarps];

    const int tid    = threadIdx.x;
    const int lane   = tid & 31;
    const int wid    = tid >> 5;
    const int stride = gridDim.x;

    if (tid == 0) {
        #pragma unroll
        for (int b = 0; b < kNBuf; ++b)
            asm volatile("mbarrier.init.shared::cta.b64 [%0], 1;"
                         :: "r"(s2u(&mbar[b])) : "memory");
    }
    __syncthreads();

    const int nIter = (rows - (int)blockIdx.x + stride - 1) / stride;
    if (nIter <= 0) return;

    // prologue: first row's load into buffer 0
    if (tid == 0) {
        const uint32_t mb = s2u(&mbar[0]);
        mbar_expect_tx(mb, kRowBytes);
        bulk_load(s2u(smem), x + (size_t)blockIdx.x * kT, kRowBytes, mb);
    }

    for (int it = 0; it < nIter; ++it) {
        const int row  = blockIdx.x + it * stride;
        const int bsel = it & 1;
        float* sx = smem + bsel * kT;

        // issue next row's load into the other buffer.
        // That buffer holds row it-1 whose bulk store (committed end of it-1)
        // must have finished READING smem first.
        if (tid == 0 && it + 1 < nIter) {
            asm volatile("cp.async.bulk.wait_group.read 0;" ::: "memory");
            const int nb = bsel ^ 1;
            const uint32_t mb = s2u(&mbar[nb]);
            mbar_expect_tx(mb, kRowBytes);
            bulk_load(s2u(smem + nb * kT), x + (size_t)(row + stride) * kT, kRowBytes, mb);
        }

        // per-row params (warp-uniform)
        const int   c  = row % C;
        const float w  = fminf(fmaxf(ew[c], 0.0f), 1.0f);
        const float q  = 1.0f - w;
        const float a  = fminf(alpha[c], 1.0f);
        const float d  = delta[c];
        const float r  = 1.0f / fmaxf(root[c], 1.0f);
        const bool  rhalf = (r == 0.5f);
        const float dr = rhalf ? sqrt_apx(d) : __powf(d, r);
        const float na = -a;

        // wait for this row's data (buffer reused every 2 iterations)
        mbar_wait(s2u(&mbar[bsel]), (it >> 1) & 1);

        const float x0  = sx[0];
        const int   off = tid * kChunk;

        // pass 1: per-thread affine reduce over the 25-element chunk
        float b = 0.0f;
        #pragma unroll
        for (int k = 0; k < kChunk; ++k)
            b = fmaf(q, b, sx[off + k]);
        b *= w;
        const float q2 = q*q, q4 = q2*q2, q8 = q4*q4, q16 = q8*q8;
        float A = q16 * q8 * q;   // q^25

        // warp inclusive scan of (A,b):  cur ∘ prev
        #pragma unroll
        for (int s = 1; s < 32; s <<= 1) {
            float Ap = __shfl_up_sync(0xffffffffu, A, s);
            float bp = __shfl_up_sync(0xffffffffu, b, s);
            if (lane >= s) { b = fmaf(A, bp, b); A *= Ap; }
        }
        if (lane == 31) { sA[wid] = A; sB[wid] = b; }
        __syncthreads();

        // every warp redundantly scans the 10 warp aggregates (1 barrier total)
        float Aw = (lane < kWarps) ? sA[lane] : 1.0f;
        float bw = (lane < kWarps) ? sB[lane] : 0.0f;
        #pragma unroll
        for (int s = 1; s < 16; s <<= 1) {
            float Ap = __shfl_up_sync(0xffffffffu, Aw, s);
            float bp = __shfl_up_sync(0xffffffffu, bw, s);
            if (lane >= s) { bw = fmaf(Aw, bp, bw); Aw *= Ap; }
        }
        // prefix over warps < wid lives at lane wid-1
        const int   src = (wid > 0) ? (wid - 1) : 0;
        float ApX = __shfl_sync(0xffffffffu, Aw, src);
        float bpX = __shfl_sync(0xffffffffu, bw, src);
        if (wid == 0) { ApX = 1.0f; bpX = 0.0f; }

        // thread-exclusive within warp
        float Ai = __shfl_up_sync(0xffffffffu, A, 1);
        float bi = __shfl_up_sync(0xffffffffu, b, 1);
        if (lane == 0) { Ai = 1.0f; bi = 0.0f; }

        // composed exclusive prefix: Ei ∘ P
        const float Aex = Ai * ApX;
        const float bex = fmaf(Ai, bpX, bi);
        float acc = fmaf(Aex, x0, bex);   // exact carry into this chunk

        // pass 2: EMA recompute + pointwise PCEN, written in place
        #pragma unroll
        for (int k = 0; k < kChunk; ++k) {
            const float xv = sx[off + k];
            acc = fmaf(q, acc, w * xv);
            const float p = __powf(kFloor + acc, na);      // LG2+FMUL+EX2
            const float u = fmaf(xv, p, d);
            const float y = rhalf ? sqrt_apx(u) : __powf(u, r);
            sx[off + k] = y - dr;
        }
        __syncthreads();

        // async bulk store smem -> gmem (reads smem asynchronously)
        if (tid == 0) {
            asm volatile("fence.proxy.async.shared::cta;" ::: "memory");
            asm volatile("cp.async.bulk.global.shared::cta.bulk_group [%0], [%1], %2;"
                         :: "l"(out + (size_t)row * kT), "r"(s2u(sx)), "r"(kRowBytes)
                         : "memory");
            asm volatile("cp.async.bulk.commit_group;" ::: "memory");
        }
    }

    // smem freed at CTA exit; ensure pending store finished reading it
    if (tid == 0)
        asm volatile("cp.async.bulk.wait_group 0;" ::: "memory");
}

extern "C" void kernel_launch(void* const* d_in, const int* in_sizes, int n_in,
                              void* d_out, int out_size)
{
    const float* x     = (const float*)d_in[0];
    const float* alpha = (const float*)d_in[1];
    const float* delta = (const float*)d_in[2];
    const float* root  = (const float*)d_in[3];
    const float* ew    = (const float*)d_in[4];
    float* out = (float*)d_out;

    const int C    = in_sizes[1];            // 64
    const int rows = in_sizes[0] / kT;       // 8192

    const unsigned smemBytes = kNBuf * kRowBytes;   // 64000 per CTA
    cudaFuncSetAttribute(pcen_kernel, cudaFuncAttributeMaxDynamicSharedMemorySize, smemBytes);

    int grid = 148 * 3;                      // 3 persistent CTAs per SM
    if (grid > rows) grid = rows;

    pcen_kernel<<<grid, kThreads, smemBytes>>>(x, alpha, delta, root, ew, out, C, rows);
}

// round 5
// speedup vs baseline: 1.8639x; 1.0706x over previous
#include <cuda_runtime.h>
#include <cstdint>

// PCEN, 1 row per CTA (grid = B*C = 8192), bulk-async load, per-warp eager
// bulk stores. 4 CTAs/SM resident; CLC relaunch provides pipelining and
// natural phase decorrelation across CTAs.
//   ema_t = w*x_t + (1-w)*ema_{t-1}, ema_0 = x_0   (affine block scan, exact)
//   out   = (x/(FLOOR+ema)^a + d)^(1/root) - d^(1/root)

constexpr int      kT        = 8000;
constexpr int      kChunk    = 25;            // 320*25 = 8000; 25 coprime 32 -> no bank conflicts
constexpr int      kThreads  = 320;
constexpr int      kWarps    = kThreads / 32; // 10
constexpr float    kFloor    = 1e-6f;
constexpr unsigned kRowBytes = kT * 4;                    // 32000
constexpr unsigned kWarpBytes = 32 * kChunk * 4;          // 3200 per-warp store

__device__ __forceinline__ uint32_t s2u(const void* p) {
    return (uint32_t)__cvta_generic_to_shared(p);
}

__device__ __forceinline__ float sqrt_apx(float v) {
    float r;
    asm("sqrt.approx.f32 %0, %1;" : "=f"(r) : "f"(v));
    return r;
}

__device__ __forceinline__ void bulk_load(uint32_t dst_smem, const void* src_gmem,
                                          uint32_t bytes, uint32_t mbar) {
    asm volatile(
        "cp.async.bulk.shared::cta.global.mbarrier::complete_tx::bytes [%0], [%1], %2, [%3];"
        :: "r"(dst_smem), "l"(src_gmem), "r"(bytes), "r"(mbar) : "memory");
}

__device__ __forceinline__ void mbar_expect_tx(uint32_t mbar, uint32_t bytes) {
    asm volatile("mbarrier.arrive.expect_tx.shared::cta.b64 _, [%0], %1;"
                 :: "r"(mbar), "r"(bytes) : "memory");
}

__device__ __forceinline__ void mbar_wait(uint32_t mbar, uint32_t phase) {
    asm volatile(
        "{\n\t.reg .pred P;\n"
        "W_%=:\n\t"
        "mbarrier.try_wait.parity.acquire.cta.shared::cta.b64 P, [%0], %1, 0x989680;\n\t"
        "@!P bra W_%=;\n\t}"
        :: "r"(mbar), "r"(phase) : "memory");
}

__global__ void __launch_bounds__(kThreads, 4)
pcen_kernel(const float* __restrict__ x,
            const float* __restrict__ alpha,
            const float* __restrict__ delta,
            const float* __restrict__ root,
            const float* __restrict__ ew,
            float* __restrict__ out,
            int C)
{
    __shared__ float sx[kT];
    __shared__ __align__(8) unsigned long long mbar;
    __shared__ float sA[kWarps], sB[kWarps];

    const int tid  = threadIdx.x;
    const int lane = tid & 31;
    const int wid  = tid >> 5;
    const int row  = blockIdx.x;

    // kick off the row load ASAP
    if (tid == 0) {
        const uint32_t mb = s2u(&mbar);
        asm volatile("mbarrier.init.shared::cta.b64 [%0], 1;" :: "r"(mb) : "memory");
        mbar_expect_tx(mb, kRowBytes);
        bulk_load(s2u(sx), x + (size_t)row * kT, kRowBytes, mb);
    }

    // per-row params (warp-uniform); loads overlap the bulk-load latency
    const int   c  = row % C;
    const float w  = fminf(fmaxf(ew[c], 0.0f), 1.0f);
    const float q  = 1.0f - w;
    const float a  = fminf(alpha[c], 1.0f);
    const float d  = delta[c];
    const float r  = 1.0f / fmaxf(root[c], 1.0f);
    const bool  rhalf = (r == 0.5f);
    const float dr = rhalf ? sqrt_apx(d) : __powf(d, r);
    const float na = -a;

    // make mbar init visible to all threads, then wait for data
    __syncthreads();
    mbar_wait(s2u(&mbar), 0);

    const float x0  = sx[0];
    const int   off = tid * kChunk;

    // pass 1: per-thread affine reduce over the 25-element chunk
    float b = 0.0f;
    #pragma unroll
    for (int k = 0; k < kChunk; ++k)
        b = fmaf(q, b, sx[off + k]);
    b *= w;
    const float q2 = q*q, q4 = q2*q2, q8 = q4*q4, q16 = q8*q8;
    float A = q16 * q8 * q;   // q^25

    // warp inclusive scan of (A,b)
    #pragma unroll
    for (int s = 1; s < 32; s <<= 1) {
        float Ap = __shfl_up_sync(0xffffffffu, A, s);
        float bp = __shfl_up_sync(0xffffffffu, b, s);
        if (lane >= s) { b = fmaf(A, bp, b); A *= Ap; }
    }
    if (lane == 31) { sA[wid] = A; sB[wid] = b; }
    __syncthreads();

    // every warp redundantly scans the 10 warp aggregates (single barrier)
    float Aw = (lane < kWarps) ? sA[lane] : 1.0f;
    float bw = (lane < kWarps) ? sB[lane] : 0.0f;
    #pragma unroll
    for (int s = 1; s < 16; s <<= 1) {
        float Ap = __shfl_up_sync(0xffffffffu, Aw, s);
        float bp = __shfl_up_sync(0xffffffffu, bw, s);
        if (lane >= s) { bw = fmaf(Aw, bp, bw); Aw *= Ap; }
    }
    const int src = (wid > 0) ? (wid - 1) : 0;
    float ApX = __shfl_sync(0xffffffffu, Aw, src);
    float bpX = __shfl_sync(0xffffffffu, bw, src);
    if (wid == 0) { ApX = 1.0f; bpX = 0.0f; }

    // thread-exclusive prefix within warp, composed with warp prefix
    float Ai = __shfl_up_sync(0xffffffffu, A, 1);
    float bi = __shfl_up_sync(0xffffffffu, b, 1);
    if (lane == 0) { Ai = 1.0f; bi = 0.0f; }
    const float Aex = Ai * ApX;
    const float bex = fmaf(Ai, bpX, bi);
    float acc = fmaf(Aex, x0, bex);   // exact carry into this chunk

    // pass 2: EMA recompute + pointwise PCEN, written in place
    #pragma unroll
    for (int k = 0; k < kChunk; ++k) {
        const float xv = sx[off + k];
        acc = fmaf(q, acc, w * xv);
        const float p = __powf(kFloor + acc, na);      // MUFU lg2 + ex2
        const float u = fmaf(xv, p, d);
        const float y = rhalf ? sqrt_apx(u) : __powf(u, r);
        sx[off + k] = y - dr;
    }

    // per-warp eager bulk store: drain this warp's 3200B as soon as it's done
    __syncwarp();
    if (lane == 0) {
        asm volatile("fence.proxy.async.shared::cta;" ::: "memory");
        asm volatile("cp.async.bulk.global.shared::cta.bulk_group [%0], [%1], %2;"
                     :: "l"(out + (size_t)row * kT + wid * (32 * kChunk)),
                        "r"(s2u(sx + wid * (32 * kChunk))), "r"(kWarpBytes)
                     : "memory");
        asm volatile("cp.async.bulk.commit_group;" ::: "memory");
        // smem must stay valid until the store has read it; CTA keeps smem
        // alive until ALL threads exit, and this thread holds until read-done.
        asm volatile("cp.async.bulk.wait_group.read 0;" ::: "memory");
    }
}

extern "C" void kernel_launch(void* const* d_in, const int* in_sizes, int n_in,
                              void* d_out, int out_size)
{
    const float* x     = (const float*)d_in[0];
    const float* alpha = (const float*)d_in[1];
    const float* delta = (const float*)d_in[2];
    const float* root  = (const float*)d_in[3];
    const float* ew    = (const float*)d_in[4];
    float* out = (float*)d_out;

    const int C    = in_sizes[1];            // 64
    const int rows = in_sizes[0] / kT;       // 8192

    pcen_kernel<<<rows, kThreads>>>(x, alpha, delta, root, ew, out, C);
}

// round 6
// speedup vs baseline: 1.8784x; 1.0078x over previous
#include <cuda_runtime.h>
#include <cstdint>

// PCEN, 1 row per CTA (grid = 8192). Row loaded as TWO 16KB bulk copies with
// separate mbarriers so the lower-half warps start pass 1 while the upper half
// is still in flight. Per-warp eager bulk stores. L2 evict_first hints
// (pure streaming; keep the 126MB L2 from thrashing).
//   ema_t = w*x_t + (1-w)*ema_{t-1}, ema_0 = x_0   (affine block scan, exact)
//   out   = (x/(FLOOR+ema)^a + d)^(1/root) - d^(1/root)

constexpr int      kT         = 8000;
constexpr int      kChunk     = 25;            // 320*25 = 8000; 25 coprime 32 -> no bank conflicts
constexpr int      kThreads   = 320;
constexpr int      kWarps     = kThreads / 32; // 10
constexpr float    kFloor     = 1e-6f;
constexpr int      kHalfElems = kT / 2;                    // 4000 = warps 0-4's span
constexpr unsigned kHalfBytes = kHalfElems * 4;            // 16000
constexpr unsigned kWarpBytes = 32 * kChunk * 4;           // 3200 per-warp store

__device__ __forceinline__ uint32_t s2u(const void* p) {
    return (uint32_t)__cvta_generic_to_shared(p);
}

__device__ __forceinline__ float sqrt_apx(float v) {
    float r;
    asm("sqrt.approx.f32 %0, %1;" : "=f"(r) : "f"(v));
    return r;
}

__device__ __forceinline__ uint64_t evict_first_policy() {
    uint64_t pol;
    asm("createpolicy.fractional.L2::evict_first.b64 %0, 1.0;" : "=l"(pol));
    return pol;
}

__device__ __forceinline__ void bulk_load_hint(uint32_t dst_smem, const void* src_gmem,
                                               uint32_t bytes, uint32_t mbar, uint64_t pol) {
    asm volatile(
        "cp.async.bulk.shared::cta.global.mbarrier::complete_tx::bytes.L2::cache_hint"
        " [%0], [%1], %2, [%3], %4;"
        :: "r"(dst_smem), "l"(src_gmem), "r"(bytes), "r"(mbar), "l"(pol) : "memory");
}

__device__ __forceinline__ void mbar_expect_tx(uint32_t mbar, uint32_t bytes) {
    asm volatile("mbarrier.arrive.expect_tx.shared::cta.b64 _, [%0], %1;"
                 :: "r"(mbar), "r"(bytes) : "memory");
}

__device__ __forceinline__ void mbar_wait(uint32_t mbar, uint32_t phase) {
    asm volatile(
        "{\n\t.reg .pred P;\n"
        "W_%=:\n\t"
        "mbarrier.try_wait.parity.acquire.cta.shared::cta.b64 P, [%0], %1, 0x989680;\n\t"
        "@!P bra W_%=;\n\t}"
        :: "r"(mbar), "r"(phase) : "memory");
}

__global__ void __launch_bounds__(kThreads, 4)
pcen_kernel(const float* __restrict__ x,
            const float* __restrict__ alpha,
            const float* __restrict__ delta,
            const float* __restrict__ root,
            const float* __restrict__ ew,
            float* __restrict__ out,
            int C)
{
    __shared__ float sx[kT];
    __shared__ __align__(8) unsigned long long mbar[2];
    __shared__ float sA[kWarps], sB[kWarps];

    const int tid  = threadIdx.x;
    const int lane = tid & 31;
    const int wid  = tid >> 5;
    const int row  = blockIdx.x;

    const uint64_t pol = evict_first_policy();

    // kick off both half-row loads ASAP
    if (tid == 0) {
        const uint32_t mb0 = s2u(&mbar[0]);
        const uint32_t mb1 = s2u(&mbar[1]);
        asm volatile("mbarrier.init.shared::cta.b64 [%0], 1;" :: "r"(mb0) : "memory");
        asm volatile("mbarrier.init.shared::cta.b64 [%0], 1;" :: "r"(mb1) : "memory");
        const float* src = x + (size_t)row * kT;
        mbar_expect_tx(mb0, kHalfBytes);
        bulk_load_hint(s2u(sx), src, kHalfBytes, mb0, pol);
        mbar_expect_tx(mb1, kHalfBytes);
        bulk_load_hint(s2u(sx + kHalfElems), src + kHalfElems, kHalfBytes, mb1, pol);
    }

    // per-row params (warp-uniform); overlaps the bulk-load latency
    const int   c  = row % C;
    const float w  = fminf(fmaxf(ew[c], 0.0f), 1.0f);
    const float q  = 1.0f - w;
    const float a  = fminf(alpha[c], 1.0f);
    const float d  = delta[c];
    const float r  = 1.0f / fmaxf(root[c], 1.0f);
    const bool  rhalf = (r == 0.5f);
    const float dr = rhalf ? sqrt_apx(d) : __powf(d, r);
    const float na = -a;

    // make mbar init visible to all threads, then wait only for OUR half
    __syncthreads();
    mbar_wait(s2u(&mbar[wid < (kWarps / 2) ? 0 : 1]), 0);

    const int off = tid * kChunk;

    // pass 1: per-thread affine reduce over the 25-element chunk
    float b = 0.0f;
    #pragma unroll
    for (int k = 0; k < kChunk; ++k)
        b = fmaf(q, b, sx[off + k]);
    b *= w;
    const float q2 = q*q, q4 = q2*q2, q8 = q4*q4, q16 = q8*q8;
    float A = q16 * q8 * q;   // q^25

    // warp inclusive scan of (A,b)
    #pragma unroll
    for (int s = 1; s < 32; s <<= 1) {
        float Ap = __shfl_up_sync(0xffffffffu, A, s);
        float bp = __shfl_up_sync(0xffffffffu, b, s);
        if (lane >= s) { b = fmaf(A, bp, b); A *= Ap; }
    }
    if (lane == 31) { sA[wid] = A; sB[wid] = b; }
    __syncthreads();

    // every warp redundantly scans the 10 warp aggregates (single barrier)
    float Aw = (lane < kWarps) ? sA[lane] : 1.0f;
    float bw = (lane < kWarps) ? sB[lane] : 0.0f;
    #pragma unroll
    for (int s = 1; s < 16; s <<= 1) {
        float Ap = __shfl_up_sync(0xffffffffu, Aw, s);
        float bp = __shfl_up_sync(0xffffffffu, bw, s);
        if (lane >= s) { bw = fmaf(Aw, bp, bw); Aw *= Ap; }
    }
    const int src = (wid > 0) ? (wid - 1) : 0;
    float ApX = __shfl_sync(0xffffffffu, Aw, src);
    float bpX = __shfl_sync(0xffffffffu, bw, src);
    if (wid == 0) { ApX = 1.0f; bpX = 0.0f; }

    // thread-exclusive prefix within warp, composed with warp prefix
    float Ai = __shfl_up_sync(0xffffffffu, A, 1);
    float bi = __shfl_up_sync(0xffffffffu, b, 1);
    if (lane == 0) { Ai = 1.0f; bi = 0.0f; }
    const float Aex = Ai * ApX;
    const float bex = fmaf(Ai, bpX, bi);
    const float x0  = sx[0];          // first half guaranteed present (post-barrier)
    float acc = fmaf(Aex, x0, bex);   // exact carry into this chunk

    // pass 2: EMA recompute + pointwise PCEN, written in place
    #pragma unroll
    for (int k = 0; k < kChunk; ++k) {
        const float xv = sx[off + k];
        acc = fmaf(q, acc, w * xv);
        const float p = __powf(kFloor + acc, na);      // MUFU lg2 + ex2
        const float u = fmaf(xv, p, d);
        const float y = rhalf ? sqrt_apx(u) : __powf(u, r);
        sx[off + k] = y - dr;
    }

    // per-warp eager bulk store: drain this warp's 3200B as soon as it's done
    __syncwarp();
    if (lane == 0) {
        asm volatile("fence.proxy.async.shared::cta;" ::: "memory");
        asm volatile(
            "cp.async.bulk.global.shared::cta.bulk_group.L2::cache_hint [%0], [%1], %2, %3;"
            :: "l"(out + (size_t)row * kT + wid * (32 * kChunk)),
               "r"(s2u(sx + wid * (32 * kChunk))), "r"(kWarpBytes), "l"(pol)
            : "memory");
        asm volatile("cp.async.bulk.commit_group;" ::: "memory");
        // smem must stay valid until the store has read it
        asm volatile("cp.async.bulk.wait_group.read 0;" ::: "memory");
    }
}

extern "C" void kernel_launch(void* const* d_in, const int* in_sizes, int n_in,
                              void* d_out, int out_size)
{
    const float* x     = (const float*)d_in[0];
    const float* alpha = (const float*)d_in[1];
    const float* delta = (const float*)d_in[2];
    const float* root  = (const float*)d_in[3];
    const float* ew    = (const float*)d_in[4];
    float* out = (float*)d_out;

    const int C    = in_sizes[1];            // 64
    const int rows = in_sizes[0] / kT;       // 8192

    pcen_kernel<<<rows, kThreads>>>(x, alpha, delta, root, ew, out, C);
}

// round 7
// speedup vs baseline: 1.8791x; 1.0004x over previous
#include <cuda_runtime.h>
#include <cstdint>

// PCEN, 1 row per CTA (grid = 8192), 6 CTAs/SM resident (60 warps) to keep
// DRAM and MUFU both fed from independent row pipelines.
// Row loaded as two 16KB bulk copies (separate mbarriers); per-warp eager
// bulk stores; L2 evict_first hints.
//   ema_t = w*x_t + (1-w)*ema_{t-1}, ema_0 = x_0   (affine block scan, exact)
//   out   = (x/(FLOOR+ema)^a + d)^(1/root) - d^(1/root)

constexpr int      kT         = 8000;
constexpr int      kChunk     = 25;            // 320*25 = 8000; 25 coprime 32 -> no bank conflicts
constexpr int      kThreads   = 320;
constexpr int      kWarps     = kThreads / 32; // 10
constexpr float    kFloor     = 1e-6f;
constexpr int      kHalfElems = kT / 2;                    // 4000
constexpr unsigned kHalfBytes = kHalfElems * 4;            // 16000
constexpr unsigned kWarpBytes = 32 * kChunk * 4;           // 3200 per-warp store

__device__ __forceinline__ uint32_t s2u(const void* p) {
    return (uint32_t)__cvta_generic_to_shared(p);
}

__device__ __forceinline__ float sqrt_apx(float v) {
    float r;
    asm("sqrt.approx.f32 %0, %1;" : "=f"(r) : "f"(v));
    return r;
}

__device__ __forceinline__ uint64_t evict_first_policy() {
    uint64_t pol;
    asm("createpolicy.fractional.L2::evict_first.b64 %0, 1.0;" : "=l"(pol));
    return pol;
}

__device__ __forceinline__ void bulk_load_hint(uint32_t dst_smem, const void* src_gmem,
                                               uint32_t bytes, uint32_t mbar, uint64_t pol) {
    asm volatile(
        "cp.async.bulk.shared::cta.global.mbarrier::complete_tx::bytes.L2::cache_hint"
        " [%0], [%1], %2, [%3], %4;"
        :: "r"(dst_smem), "l"(src_gmem), "r"(bytes), "r"(mbar), "l"(pol) : "memory");
}

__device__ __forceinline__ void mbar_expect_tx(uint32_t mbar, uint32_t bytes) {
    asm volatile("mbarrier.arrive.expect_tx.shared::cta.b64 _, [%0], %1;"
                 :: "r"(mbar), "r"(bytes) : "memory");
}

__device__ __forceinline__ void mbar_wait(uint32_t mbar, uint32_t phase) {
    asm volatile(
        "{\n\t.reg .pred P;\n"
        "W_%=:\n\t"
        "mbarrier.try_wait.parity.acquire.cta.shared::cta.b64 P, [%0], %1, 0x989680;\n\t"
        "@!P bra W_%=;\n\t}"
        :: "r"(mbar), "r"(phase) : "memory");
}

__global__ void __launch_bounds__(kThreads, 6)
pcen_kernel(const float* __restrict__ x,
            const float* __restrict__ alpha,
            const float* __restrict__ delta,
            const float* __restrict__ root,
            const float* __restrict__ ew,
            float* __restrict__ out,
            int C)
{
    __shared__ float sx[kT];
    __shared__ __align__(8) unsigned long long mbar[2];
    __shared__ float sA[kWarps], sB[kWarps];

    const int tid  = threadIdx.x;
    const int lane = tid & 31;
    const int wid  = tid >> 5;
    const int row  = blockIdx.x;

    const uint64_t pol = evict_first_policy();

    // kick off both half-row loads ASAP
    if (tid == 0) {
        const uint32_t mb0 = s2u(&mbar[0]);
        const uint32_t mb1 = s2u(&mbar[1]);
        asm volatile("mbarrier.init.shared::cta.b64 [%0], 1;" :: "r"(mb0) : "memory");
        asm volatile("mbarrier.init.shared::cta.b64 [%0], 1;" :: "r"(mb1) : "memory");
        const float* src = x + (size_t)row * kT;
        mbar_expect_tx(mb0, kHalfBytes);
        bulk_load_hint(s2u(sx), src, kHalfBytes, mb0, pol);
        mbar_expect_tx(mb1, kHalfBytes);
        bulk_load_hint(s2u(sx + kHalfElems), src + kHalfElems, kHalfBytes, mb1, pol);
    }

    // per-row params (warp-uniform); overlaps the bulk-load latency
    const int   c  = row % C;
    const float w  = fminf(fmaxf(ew[c], 0.0f), 1.0f);
    const float q  = 1.0f - w;
    const float a  = fminf(alpha[c], 1.0f);
    const float d  = delta[c];
    const float r  = 1.0f / fmaxf(root[c], 1.0f);
    const bool  rhalf = (r == 0.5f);
    const float dr = rhalf ? sqrt_apx(d) : __powf(d, r);
    const float na = -a;

    // make mbar init visible to all threads, then wait only for OUR half
    __syncthreads();
    mbar_wait(s2u(&mbar[wid < (kWarps / 2) ? 0 : 1]), 0);

    const int off = tid * kChunk;

    // pass 1: per-thread affine reduce over the 25-element chunk
    float b = 0.0f;
    #pragma unroll
    for (int k = 0; k < kChunk; ++k)
        b = fmaf(q, b, sx[off + k]);
    b *= w;
    const float q2 = q*q, q4 = q2*q2, q8 = q4*q4, q16 = q8*q8;
    float A = q16 * q8 * q;   // q^25

    // warp inclusive scan of (A,b)
    #pragma unroll
    for (int s = 1; s < 32; s <<= 1) {
        float Ap = __shfl_up_sync(0xffffffffu, A, s);
        float bp = __shfl_up_sync(0xffffffffu, b, s);
        if (lane >= s) { b = fmaf(A, bp, b); A *= Ap; }
    }
    if (lane == 31) { sA[wid] = A; sB[wid] = b; }
    __syncthreads();

    // every warp redundantly scans the 10 warp aggregates (single barrier)
    float Aw = (lane < kWarps) ? sA[lane] : 1.0f;
    float bw = (lane < kWarps) ? sB[lane] : 0.0f;
    #pragma unroll
    for (int s = 1; s < 16; s <<= 1) {
        float Ap = __shfl_up_sync(0xffffffffu, Aw, s);
        float bp = __shfl_up_sync(0xffffffffu, bw, s);
        if (lane >= s) { bw = fmaf(Aw, bp, bw); Aw *= Ap; }
    }
    const int src = (wid > 0) ? (wid - 1) : 0;
    float ApX = __shfl_sync(0xffffffffu, Aw, src);
    float bpX = __shfl_sync(0xffffffffu, bw, src);
    if (wid == 0) { ApX = 1.0f; bpX = 0.0f; }

    // thread-exclusive prefix within warp, composed with warp prefix
    float Ai = __shfl_up_sync(0xffffffffu, A, 1);
    float bi = __shfl_up_sync(0xffffffffu, b, 1);
    if (lane == 0) { Ai = 1.0f; bi = 0.0f; }
    const float Aex = Ai * ApX;
    const float bex = fmaf(Ai, bpX, bi);
    const float x0  = sx[0];          // first half present (post-barrier)
    float acc = fmaf(Aex, x0, bex);   // exact carry into this chunk

    // pass 2: EMA recompute + pointwise PCEN, written in place
    #pragma unroll
    for (int k = 0; k < kChunk; ++k) {
        const float xv = sx[off + k];
        acc = fmaf(q, acc, w * xv);
        const float p = __powf(kFloor + acc, na);      // MUFU lg2 + ex2
        const float u = fmaf(xv, p, d);
        const float y = rhalf ? sqrt_apx(u) : __powf(u, r);
        sx[off + k] = y - dr;
    }

    // per-warp eager bulk store: drain this warp's 3200B as soon as it's done
    __syncwarp();
    if (lane == 0) {
        asm volatile("fence.proxy.async.shared::cta;" ::: "memory");
        asm volatile(
            "cp.async.bulk.global.shared::cta.bulk_group.L2::cache_hint [%0], [%1], %2, %3;"
            :: "l"(out + (size_t)row * kT + wid * (32 * kChunk)),
               "r"(s2u(sx + wid * (32 * kChunk))), "r"(kWarpBytes), "l"(pol)
            : "memory");
        asm volatile("cp.async.bulk.commit_group;" ::: "memory");
        // smem must stay valid until the store has read it
        asm volatile("cp.async.bulk.wait_group.read 0;" ::: "memory");
    }
}

extern "C" void kernel_launch(void* const* d_in, const int* in_sizes, int n_in,
                              void* d_out, int out_size)
{
    const float* x     = (const float*)d_in[0];
    const float* alpha = (const float*)d_in[1];
    const float* delta = (const float*)d_in[2];
    const float* root  = (const float*)d_in[3];
    const float* ew    = (const float*)d_in[4];
    float* out = (float*)d_out;

    const int C    = in_sizes[1];            // 64
    const int rows = in_sizes[0] / kT;       // 8192

    // allow 6 CTAs/SM worth of shared memory
    static bool configured = false;
    if (!configured) {
        cudaFuncSetAttribute(pcen_kernel,
                             cudaFuncAttributePreferredSharedMemoryCarveout, 100);
        configured = true;
    }

    pcen_kernel<<<rows, kThreads>>>(x, alpha, delta, root, ew, out, C);
}